// round 13
// baseline (speedup 1.0000x reference)
#include <cuda_runtime.h>
#include <cstdint>

#define N_NODES 50000
#define D 128
#define MAXDEG 96
#define SPAD 132   // padded row stride for transposed W in smem
#define RN 8       // nodes per warp in the matvec

// ---- per-launch scratch (device globals) ----
__device__ int  g_cnt[N_NODES];
__device__ int2 g_bkt[N_NODES * MAXDEG];   // {src, __float_as_int(e)} per dst

// ---------------------------------------------------------------------------
// Bucket append, 4 edges per thread (vectorized loads, batched atomics).
// ---------------------------------------------------------------------------
__global__ void fill_buckets_kernel(const int* __restrict__ esrc,
                                    const int* __restrict__ edst,
                                    const float* __restrict__ ee, int E) {
    int i = blockIdx.x * blockDim.x + threadIdx.x;
    int base = i * 4;
    if (base + 3 < E) {
        int4   s4 = *reinterpret_cast<const int4*>(esrc + base);
        int4   d4 = *reinterpret_cast<const int4*>(edst + base);
        float4 e4 = *reinterpret_cast<const float4*>(ee + base);
        int p0 = atomicAdd(&g_cnt[d4.x], 1);
        int p1 = atomicAdd(&g_cnt[d4.y], 1);
        int p2 = atomicAdd(&g_cnt[d4.z], 1);
        int p3 = atomicAdd(&g_cnt[d4.w], 1);
        if (p0 < MAXDEG) g_bkt[d4.x * MAXDEG + p0] = make_int2(s4.x, __float_as_int(e4.x));
        if (p1 < MAXDEG) g_bkt[d4.y * MAXDEG + p1] = make_int2(s4.y, __float_as_int(e4.y));
        if (p2 < MAXDEG) g_bkt[d4.z * MAXDEG + p2] = make_int2(s4.z, __float_as_int(e4.z));
        if (p3 < MAXDEG) g_bkt[d4.w * MAXDEG + p3] = make_int2(s4.w, __float_as_int(e4.w));
    } else {
        for (int k = base; k < E; k++) {
            int d = edst[k];
            int p = atomicAdd(&g_cnt[d], 1);
            if (p < MAXDEG) g_bkt[d * MAXDEG + p] = make_int2(esrc[k], __float_as_int(ee[k]));
        }
    }
}

// ---------------------------------------------------------------------------
// Packed fp32 helpers (Blackwell f32x2 pipe; ptxas won't auto-generate these)
// ---------------------------------------------------------------------------
__device__ __forceinline__ unsigned long long fma2(unsigned long long a,
                                                   unsigned long long b,
                                                   unsigned long long c) {
    unsigned long long d;
    asm("fma.rn.f32x2 %0, %1, %2, %3;" : "=l"(d) : "l"(a), "l"(b), "l"(c));
    return d;
}
__device__ __forceinline__ unsigned long long pack2(float lo, float hi) {
    unsigned long long d;
    asm("mov.b64 %0, {%1, %2};" : "=l"(d) : "f"(lo), "f"(hi));
    return d;
}
__device__ __forceinline__ float2 unpack2(unsigned long long v) {
    float lo, hi;
    asm("mov.b64 {%0, %1}, %2;" : "=f"(lo), "=f"(hi) : "l"(v));
    return make_float2(lo, hi);
}

// ---------------------------------------------------------------------------
// Fused: R12 gather (double-buffered stage, SHFL, MLP 8; r-loop NOT unrolled
// to contain registers) + R=8 matvec (f4-broadcast S, packed f32x2 FMA).
// out[n] = relu((W @ S[n] + b*c[n]) / max(deg[n],1)) + alpha[n]*feat[n]
// ---------------------------------------------------------------------------
__global__ void __launch_bounds__(256, 2) fused_kernel(
    const float* __restrict__ feat, const float* __restrict__ alpha,
    const float* __restrict__ W, const float* __restrict__ b,
    float* __restrict__ out) {
    extern __shared__ float smx[];
    float* Ws = smx;                       // [D][SPAD]  Ws[k*SPAD+i] = W[i][k]
    float* Ss = smx + D * SPAD;            // [8 warps][RN][D]
    float2* Cd = reinterpret_cast<float2*>(Ss + 8 * RN * D);  // [8 warps][RN] {c, deg}

    int tid = threadIdx.x, warp = tid >> 5, lane = tid & 31;

    for (int idx = tid; idx < D * D; idx += blockDim.x) {
        int i = idx >> 7;                  // output dim
        int k = idx & (D - 1);             // input dim
        Ws[k * SPAD + i] = W[idx];
    }
    __syncthreads();

    const int oi = lane * 4;
    float4 bb = *reinterpret_cast<const float4*>(b + oi);
    float* ss = Ss + warp * (RN * D);
    float2* cd = Cd + warp * RN;
    const float4* feat4 = reinterpret_cast<const float4*>(feat);
    const unsigned fullm = 0xffffffffu;

    const int NPT = 8 * RN;                // 64 nodes per block-tile
    const int numTiles = (N_NODES + NPT - 1) / NPT;
    for (int tile = blockIdx.x; tile < numTiles; tile += gridDim.x) {
        int n0 = tile * NPT + warp * RN;

        // ---- gather phase (r-loop intentionally not unrolled) ----
        int2 pr = g_bkt[(size_t)min(n0, N_NODES - 1) * MAXDEG + lane];
        for (int r = 0; r < RN; r++) {
            // prefetch next node's stage while this node accumulates
            int rn = min(n0 + r + 1, N_NODES - 1);
            int2 prn = g_bkt[(size_t)rn * MAXDEG + lane];

            int n = n0 + r;
            int nc = min(n, N_NODES - 1);
            int cnt = (n < N_NODES) ? min(g_cnt[nc], MAXDEG) : 0;
            float4 a = make_float4(0.f, 0.f, 0.f, 0.f);
            float c = 0.f;

            {   // first 32 entries from the prefetched stage
                int   sl = pr.x;
                float el = (lane < cnt) ? __int_as_float(pr.y) : 0.f;
                int m = min(cnt, 32);
                for (int j = 0; j < m; j += 8) {
                    int   s8[8]; float e8[8];
                    #pragma unroll
                    for (int t = 0; t < 8; t++) {
                        s8[t] = __shfl_sync(fullm, sl, j + t);
                        e8[t] = __shfl_sync(fullm, el, j + t);
                    }
                    float4 v[8];
                    #pragma unroll
                    for (int t = 0; t < 8; t++)
                        v[t] = feat4[(size_t)s8[t] * 32 + lane];
                    #pragma unroll
                    for (int t = 0; t < 8; t++) {
                        a.x += e8[t] * v[t].x;
                        a.y += e8[t] * v[t].y;
                        a.z += e8[t] * v[t].z;
                        a.w += e8[t] * v[t].w;
                        c += e8[t];
                    }
                }
            }
            if (cnt > 32) {   // rare tail: deg > 32
                const int2* bp = g_bkt + (size_t)nc * MAXDEG;
                for (int base = 32; base < cnt; base += 32) {
                    int idx = base + lane;
                    int2 q2 = (idx < cnt) ? bp[idx] : make_int2(0, 0);
                    int   sl = q2.x;
                    float el = (idx < cnt) ? __int_as_float(q2.y) : 0.f;
                    int m = min(cnt - base, 32);
                    for (int j = 0; j < m; j += 8) {
                        #pragma unroll
                        for (int t = 0; t < 8; t++) {
                            int   s = __shfl_sync(fullm, sl, j + t);
                            float e = __shfl_sync(fullm, el, j + t);
                            float4 v = feat4[(size_t)s * 32 + lane];
                            a.x += e * v.x; a.y += e * v.y;
                            a.z += e * v.z; a.w += e * v.w;
                            c += e;
                        }
                    }
                }
            }
            reinterpret_cast<float4*>(ss + r * D)[lane] = a;
            if (lane == 0) cd[r] = make_float2(c, (float)cnt);  // warp-uniform
            pr = prn;
        }
        __syncwarp();

        // ---- matvec: R=8, f4-uniform-broadcast S, packed f32x2 FMA ----
        unsigned long long acc2[RN][2];
        #pragma unroll
        for (int r = 0; r < RN; r++) { acc2[r][0] = 0ull; acc2[r][1] = 0ull; }

        for (int k4 = 0; k4 < D / 4; k4++) {
            unsigned long long wp[4][2];
            #pragma unroll
            for (int t = 0; t < 4; t++) {
                float4 w = *reinterpret_cast<const float4*>(&Ws[(k4 * 4 + t) * SPAD + oi]);
                wp[t][0] = pack2(w.x, w.y);
                wp[t][1] = pack2(w.z, w.w);
            }
            #pragma unroll
            for (int r = 0; r < RN; r++) {
                float4 sv = *reinterpret_cast<const float4*>(&ss[r * D + k4 * 4]);
                unsigned long long s0 = pack2(sv.x, sv.x);
                unsigned long long s1 = pack2(sv.y, sv.y);
                unsigned long long s2 = pack2(sv.z, sv.z);
                unsigned long long s3 = pack2(sv.w, sv.w);
                acc2[r][0] = fma2(wp[0][0], s0, acc2[r][0]);
                acc2[r][1] = fma2(wp[0][1], s0, acc2[r][1]);
                acc2[r][0] = fma2(wp[1][0], s1, acc2[r][0]);
                acc2[r][1] = fma2(wp[1][1], s1, acc2[r][1]);
                acc2[r][0] = fma2(wp[2][0], s2, acc2[r][0]);
                acc2[r][1] = fma2(wp[2][1], s2, acc2[r][1]);
                acc2[r][0] = fma2(wp[3][0], s3, acc2[r][0]);
                acc2[r][1] = fma2(wp[3][1], s3, acc2[r][1]);
            }
        }

        #pragma unroll
        for (int r = 0; r < RN; r++) {
            int n = n0 + r;
            if (n < N_NODES) {
                float2 a01 = unpack2(acc2[r][0]);
                float2 a23 = unpack2(acc2[r][1]);
                float2 cdv = cd[r];
                float cv = cdv.x;
                float inv = 1.0f / fmaxf(cdv.y, 1.0f);
                float av = alpha[n];
                float4 f = feat4[(size_t)n * 32 + lane];
                float4 o;
                o.x = fmaxf((a01.x + bb.x * cv) * inv, 0.f) + av * f.x;
                o.y = fmaxf((a01.y + bb.y * cv) * inv, 0.f) + av * f.y;
                o.z = fmaxf((a23.x + bb.z * cv) * inv, 0.f) + av * f.z;
                o.w = fmaxf((a23.y + bb.w * cv) * inv, 0.f) + av * f.w;
                reinterpret_cast<float4*>(out + (size_t)n * D)[lane] = o;
            }
        }
        __syncwarp();
    }
}

extern "C" void kernel_launch(void* const* d_in, const int* in_sizes, int n_in,
                              void* d_out, int out_size) {
    const float* feat  = (const float*)d_in[0];
    const float* alpha = (const float*)d_in[1];
    const int*   esrc  = (const int*)d_in[2];
    const int*   edst  = (const int*)d_in[3];
    const float* ee    = (const float*)d_in[4];
    const float* W     = (const float*)d_in[5];
    const float* b     = (const float*)d_in[6];
    float* out = (float*)d_out;
    const int E = in_sizes[2];

    void* cnt_ptr = nullptr;
    cudaGetSymbolAddress(&cnt_ptr, g_cnt);
    cudaMemsetAsync(cnt_ptr, 0, N_NODES * sizeof(int));

    int fill_threads = (E + 3) / 4;
    fill_buckets_kernel<<<(fill_threads + 255) / 256, 256>>>(esrc, edst, ee, E);

    // Ws 67584B + Ss 32768B + Cd 512B = 100864B  (2 blocks/SM)
    const int smem_bytes = (D * SPAD + 8 * RN * D + 8 * RN * 2) * (int)sizeof(float);
    cudaFuncSetAttribute(fused_kernel,
                         cudaFuncAttributeMaxDynamicSharedMemorySize, smem_bytes);
    fused_kernel<<<296, 256, smem_bytes>>>(feat, alpha, W, b, out);
}

// round 15
// speedup vs baseline: 1.0271x; 1.0271x over previous
#include <cuda_runtime.h>
#include <cuda_fp16.h>
#include <cstdint>

#define N_NODES 50000
#define D 128
#define MAXDEG 96
#define SPAD 132      // padded row stride for transposed W in smem
#define CONVB 592     // blocks of the prep kernel doing fp32->fp16 conversion

// ---- per-launch scratch (device globals) ----
__device__ int    g_cnt[N_NODES];
__device__ int2   g_bkt[N_NODES * MAXDEG];   // {src, __float_as_int(e)} per dst
__device__ __half g_feat_h[N_NODES * D];     // fp16-staged feat (12.8 MB)

// bit-cast helpers (the named intrinsics don't exist; do it via reinterpret)
__device__ __forceinline__ uint32_t h2_bits(__half2 h) {
    return *reinterpret_cast<uint32_t*>(&h);
}
__device__ __forceinline__ float2 bits_f2(uint32_t u) {
    __half2 h = *reinterpret_cast<__half2*>(&u);
    return __half22float2(h);
}

// ---------------------------------------------------------------------------
// Prep: block-range split. Blocks [0,CONVB) convert feat fp32->fp16
// (grid-stride); remaining blocks bucket-append 4 edges/thread.
// ---------------------------------------------------------------------------
__global__ void prep_kernel(const int* __restrict__ esrc,
                            const int* __restrict__ edst,
                            const float* __restrict__ ee,
                            const float* __restrict__ feat, int E) {
    if (blockIdx.x < CONVB) {
        int tid = blockIdx.x * blockDim.x + threadIdx.x;
        int stride = CONVB * blockDim.x;
        const float4* f4 = reinterpret_cast<const float4*>(feat);
        uint2* h4 = reinterpret_cast<uint2*>(g_feat_h);
        const int total = N_NODES * D / 4;
        for (int i = tid; i < total; i += stride) {
            float4 v = f4[i];
            uint2 o;
            o.x = h2_bits(__floats2half2_rn(v.x, v.y));
            o.y = h2_bits(__floats2half2_rn(v.z, v.w));
            h4[i] = o;
        }
        return;
    }
    int i = (blockIdx.x - CONVB) * blockDim.x + threadIdx.x;
    int base = i * 4;
    if (base + 3 < E) {
        int4   s4 = *reinterpret_cast<const int4*>(esrc + base);
        int4   d4 = *reinterpret_cast<const int4*>(edst + base);
        float4 e4 = *reinterpret_cast<const float4*>(ee + base);
        int p0 = atomicAdd(&g_cnt[d4.x], 1);
        int p1 = atomicAdd(&g_cnt[d4.y], 1);
        int p2 = atomicAdd(&g_cnt[d4.z], 1);
        int p3 = atomicAdd(&g_cnt[d4.w], 1);
        if (p0 < MAXDEG) g_bkt[d4.x * MAXDEG + p0] = make_int2(s4.x, __float_as_int(e4.x));
        if (p1 < MAXDEG) g_bkt[d4.y * MAXDEG + p1] = make_int2(s4.y, __float_as_int(e4.y));
        if (p2 < MAXDEG) g_bkt[d4.z * MAXDEG + p2] = make_int2(s4.z, __float_as_int(e4.z));
        if (p3 < MAXDEG) g_bkt[d4.w * MAXDEG + p3] = make_int2(s4.w, __float_as_int(e4.w));
    } else {
        for (int k = base; k < E; k++) {
            int d = edst[k];
            int p = atomicAdd(&g_cnt[d], 1);
            if (p < MAXDEG) g_bkt[d * MAXDEG + p] = make_int2(esrc[k], __float_as_int(ee[k]));
        }
    }
}

// ---------------------------------------------------------------------------
// Packed fp32 helpers (Blackwell f32x2 pipe; ptxas won't auto-generate these)
// ---------------------------------------------------------------------------
__device__ __forceinline__ unsigned long long fma2(unsigned long long a,
                                                   unsigned long long b,
                                                   unsigned long long c) {
    unsigned long long d;
    asm("fma.rn.f32x2 %0, %1, %2, %3;" : "=l"(d) : "l"(a), "l"(b), "l"(c));
    return d;
}
__device__ __forceinline__ unsigned long long pack2(float lo, float hi) {
    unsigned long long d;
    asm("mov.b64 %0, {%1, %2};" : "=l"(d) : "f"(lo), "f"(hi));
    return d;
}
__device__ __forceinline__ float2 unpack2(unsigned long long v) {
    float lo, hi;
    asm("mov.b64 {%0, %1}, %2;" : "=f"(lo), "=f"(hi) : "l"(v));
    return make_float2(lo, hi);
}

// ---------------------------------------------------------------------------
// Fused (R12 structure; gathers read fp16-staged feat -> half the bytes,
// half the L1tex wavefronts, half the v[] registers). fp32 accumulate.
// out[n] = relu((W @ S[n] + b*c[n]) / max(deg[n],1)) + alpha[n]*feat[n]
// ---------------------------------------------------------------------------
__global__ void __launch_bounds__(256, 2) fused_kernel(
    const float* __restrict__ feat, const float* __restrict__ alpha,
    const float* __restrict__ W, const float* __restrict__ b,
    float* __restrict__ out) {
    extern __shared__ float smx[];
    float* Ws = smx;               // [D][SPAD]  Ws[k*SPAD + i] = W[i][k]
    float* Ss = smx + D * SPAD;    // [8 warps][4 nodes][D]

    int tid = threadIdx.x, warp = tid >> 5, lane = tid & 31;

    for (int idx = tid; idx < D * D; idx += blockDim.x) {
        int i = idx >> 7;          // output dim
        int k = idx & (D - 1);     // input dim
        Ws[k * SPAD + i] = W[idx];
    }
    __syncthreads();

    const int oi = lane * 4;
    float4 bb = *reinterpret_cast<const float4*>(b + oi);
    float* ss = Ss + warp * (4 * D);
    const float4* feat4 = reinterpret_cast<const float4*>(feat);
    const uint2* fh = reinterpret_cast<const uint2*>(g_feat_h);  // 8B per lane-slice
    const unsigned fullm = 0xffffffffu;

    const int numTiles = (N_NODES + 31) / 32;
    for (int tile = blockIdx.x; tile < numTiles; tile += gridDim.x) {
        int n0 = tile * 32 + warp * 4;

        // hoisted: clamp node ids, issue 4 cnt loads + first stage load early
        int nn[4];
        #pragma unroll
        for (int r = 0; r < 4; r++) { int n = n0 + r; nn[r] = (n < N_NODES) ? n : 0; }
        int craw[4];
        #pragma unroll
        for (int r = 0; r < 4; r++) craw[r] = g_cnt[nn[r]];
        int2 pr = g_bkt[(size_t)nn[0] * MAXDEG + lane];   // stage for r=0 (in flight)

        float cs[4], degs[4];
        #pragma unroll
        for (int r = 0; r < 4; r++) {
            // issue next node's stage load before consuming this one
            int2 prn;
            if (r < 3) prn = g_bkt[(size_t)nn[r + 1] * MAXDEG + lane];

            int cnt = ((n0 + r) < N_NODES) ? min(craw[r], MAXDEG) : 0;
            float4 a = make_float4(0.f, 0.f, 0.f, 0.f);
            float c = 0.f;

            // fast path: first 32 entries from the prefetched stage
            {
                int   sl = pr.x;
                float el = (lane < cnt) ? __int_as_float(pr.y) : 0.f;
                int m = min(cnt, 32);
                for (int j = 0; j < m; j += 8) {
                    int   s8[8]; float e8[8];
                    #pragma unroll
                    for (int t = 0; t < 8; t++) {
                        s8[t] = __shfl_sync(fullm, sl, j + t);
                        e8[t] = __shfl_sync(fullm, el, j + t);
                    }
                    uint2 v[8];
                    #pragma unroll
                    for (int t = 0; t < 8; t++)
                        v[t] = fh[(size_t)s8[t] * 32 + lane];
                    #pragma unroll
                    for (int t = 0; t < 8; t++) {
                        float2 f0 = bits_f2(v[t].x);
                        float2 f1 = bits_f2(v[t].y);
                        a.x += e8[t] * f0.x;
                        a.y += e8[t] * f0.y;
                        a.z += e8[t] * f1.x;
                        a.w += e8[t] * f1.y;
                        c += e8[t];
                    }
                }
            }
            // rare tail: deg > 32
            if (cnt > 32) {
                const int2* bp = g_bkt + (size_t)nn[r] * MAXDEG;
                for (int base = 32; base < cnt; base += 32) {
                    int idx = base + lane;
                    int2 q2 = (idx < cnt) ? bp[idx] : make_int2(0, 0);
                    int   sl = q2.x;
                    float el = (idx < cnt) ? __int_as_float(q2.y) : 0.f;
                    int m = min(cnt - base, 32);
                    for (int j = 0; j < m; j += 8) {
                        #pragma unroll
                        for (int t = 0; t < 8; t++) {
                            int   s = __shfl_sync(fullm, sl, j + t);
                            float e = __shfl_sync(fullm, el, j + t);
                            uint2 v = fh[(size_t)s * 32 + lane];
                            float2 f0 = bits_f2(v.x);
                            float2 f1 = bits_f2(v.y);
                            a.x += e * f0.x; a.y += e * f0.y;
                            a.z += e * f1.x; a.w += e * f1.y;
                            c += e;
                        }
                    }
                }
            }
            reinterpret_cast<float4*>(ss + r * D)[lane] = a;
            cs[r] = c;
            degs[r] = (float)cnt;
            pr = prn;
        }
        __syncwarp();

        // ---- matvec: f4-uniform-broadcast S reads, packed f32x2 FMA ----
        unsigned long long acc2[4][2];
        #pragma unroll
        for (int r = 0; r < 4; r++) { acc2[r][0] = 0ull; acc2[r][1] = 0ull; }

        for (int k4 = 0; k4 < D / 4; k4++) {
            unsigned long long wp[4][2];
            #pragma unroll
            for (int t = 0; t < 4; t++) {
                float4 w = *reinterpret_cast<const float4*>(&Ws[(k4 * 4 + t) * SPAD + oi]);
                wp[t][0] = pack2(w.x, w.y);
                wp[t][1] = pack2(w.z, w.w);
            }
            #pragma unroll
            for (int r = 0; r < 4; r++) {
                float4 sv = *reinterpret_cast<const float4*>(&ss[r * D + k4 * 4]);
                unsigned long long s0 = pack2(sv.x, sv.x);
                unsigned long long s1 = pack2(sv.y, sv.y);
                unsigned long long s2 = pack2(sv.z, sv.z);
                unsigned long long s3 = pack2(sv.w, sv.w);
                acc2[r][0] = fma2(wp[0][0], s0, acc2[r][0]);
                acc2[r][1] = fma2(wp[0][1], s0, acc2[r][1]);
                acc2[r][0] = fma2(wp[1][0], s1, acc2[r][0]);
                acc2[r][1] = fma2(wp[1][1], s1, acc2[r][1]);
                acc2[r][0] = fma2(wp[2][0], s2, acc2[r][0]);
                acc2[r][1] = fma2(wp[2][1], s2, acc2[r][1]);
                acc2[r][0] = fma2(wp[3][0], s3, acc2[r][0]);
                acc2[r][1] = fma2(wp[3][1], s3, acc2[r][1]);
            }
        }

        #pragma unroll
        for (int r = 0; r < 4; r++) {
            int n = n0 + r;
            if (n < N_NODES) {
                float2 a01 = unpack2(acc2[r][0]);
                float2 a23 = unpack2(acc2[r][1]);
                float cv = cs[r];
                float inv = 1.0f / fmaxf(degs[r], 1.0f);
                float av = alpha[n];
                float4 f = feat4[(size_t)n * 32 + lane];   // residual: fp32 exact
                float4 o;
                o.x = fmaxf((a01.x + bb.x * cv) * inv, 0.f) + av * f.x;
                o.y = fmaxf((a01.y + bb.y * cv) * inv, 0.f) + av * f.y;
                o.z = fmaxf((a23.x + bb.z * cv) * inv, 0.f) + av * f.z;
                o.w = fmaxf((a23.y + bb.w * cv) * inv, 0.f) + av * f.w;
                reinterpret_cast<float4*>(out + (size_t)n * D)[lane] = o;
            }
        }
        __syncwarp();
    }
}

extern "C" void kernel_launch(void* const* d_in, const int* in_sizes, int n_in,
                              void* d_out, int out_size) {
    const float* feat  = (const float*)d_in[0];
    const float* alpha = (const float*)d_in[1];
    const int*   esrc  = (const int*)d_in[2];
    const int*   edst  = (const int*)d_in[3];
    const float* ee    = (const float*)d_in[4];
    const float* W     = (const float*)d_in[5];
    const float* b     = (const float*)d_in[6];
    float* out = (float*)d_out;
    const int E = in_sizes[2];

    void* cnt_ptr = nullptr;
    cudaGetSymbolAddress(&cnt_ptr, g_cnt);
    cudaMemsetAsync(cnt_ptr, 0, N_NODES * sizeof(int));

    int fill_blocks = ((E + 3) / 4 + 255) / 256;
    prep_kernel<<<CONVB + fill_blocks, 256>>>(esrc, edst, ee, feat, E);

    const int smem_bytes = (D * SPAD + 8 * 4 * D) * (int)sizeof(float);  // 83968 B
    cudaFuncSetAttribute(fused_kernel,
                         cudaFuncAttributeMaxDynamicSharedMemorySize, smem_bytes);
    fused_kernel<<<296, 256, smem_bytes>>>(feat, alpha, W, b, out);
}

// round 16
// speedup vs baseline: 1.2609x; 1.2276x over previous
#include <cuda_runtime.h>
#include <cuda_fp16.h>
#include <cstdint>

#define N_NODES 50000
#define D 128
#define MAXDEG 96
#define CONVB 592     // blocks of the prep kernel doing fp32->fp16 conversion
#define SROW 136      // padded row stride (halves) for W/S smem tiles

// ---- per-launch scratch (device globals) ----
__device__ int    g_cnt[N_NODES];
__device__ int2   g_bkt[N_NODES * MAXDEG];   // {src, __float_as_int(e)} per dst
__device__ __half g_feat_h[N_NODES * D];     // fp16-staged feat (12.8 MB)

// bit-cast helpers
__device__ __forceinline__ uint32_t h2_bits(__half2 h) {
    return *reinterpret_cast<uint32_t*>(&h);
}
__device__ __forceinline__ float2 bits_f2(uint32_t u) {
    __half2 h = *reinterpret_cast<__half2*>(&u);
    return __half22float2(h);
}
__device__ __forceinline__ uint32_t smem_u32(const void* p) {
    uint32_t a;
    asm("{ .reg .u64 t; cvta.to.shared.u64 t, %1; cvt.u32.u64 %0, t; }"
        : "=r"(a) : "l"(p));
    return a;
}

// ---------------------------------------------------------------------------
// Prep: blocks [0,CONVB) convert feat fp32->fp16; rest bucket-append edges.
// ---------------------------------------------------------------------------
__global__ void prep_kernel(const int* __restrict__ esrc,
                            const int* __restrict__ edst,
                            const float* __restrict__ ee,
                            const float* __restrict__ feat, int E) {
    if (blockIdx.x < CONVB) {
        int tid = blockIdx.x * blockDim.x + threadIdx.x;
        int stride = CONVB * blockDim.x;
        const float4* f4 = reinterpret_cast<const float4*>(feat);
        uint2* h4 = reinterpret_cast<uint2*>(g_feat_h);
        const int total = N_NODES * D / 4;
        for (int i = tid; i < total; i += stride) {
            float4 v = f4[i];
            uint2 o;
            o.x = h2_bits(__floats2half2_rn(v.x, v.y));
            o.y = h2_bits(__floats2half2_rn(v.z, v.w));
            h4[i] = o;
        }
        return;
    }
    int i = (blockIdx.x - CONVB) * blockDim.x + threadIdx.x;
    int base = i * 4;
    if (base + 3 < E) {
        int4   s4 = *reinterpret_cast<const int4*>(esrc + base);
        int4   d4 = *reinterpret_cast<const int4*>(edst + base);
        float4 e4 = *reinterpret_cast<const float4*>(ee + base);
        int p0 = atomicAdd(&g_cnt[d4.x], 1);
        int p1 = atomicAdd(&g_cnt[d4.y], 1);
        int p2 = atomicAdd(&g_cnt[d4.z], 1);
        int p3 = atomicAdd(&g_cnt[d4.w], 1);
        if (p0 < MAXDEG) g_bkt[d4.x * MAXDEG + p0] = make_int2(s4.x, __float_as_int(e4.x));
        if (p1 < MAXDEG) g_bkt[d4.y * MAXDEG + p1] = make_int2(s4.y, __float_as_int(e4.y));
        if (p2 < MAXDEG) g_bkt[d4.z * MAXDEG + p2] = make_int2(s4.z, __float_as_int(e4.z));
        if (p3 < MAXDEG) g_bkt[d4.w * MAXDEG + p3] = make_int2(s4.w, __float_as_int(e4.w));
    } else {
        for (int k = base; k < E; k++) {
            int d = edst[k];
            int p = atomicAdd(&g_cnt[d], 1);
            if (p < MAXDEG) g_bkt[d * MAXDEG + p] = make_int2(esrc[k], __float_as_int(ee[k]));
        }
    }
}

// ---------------------------------------------------------------------------
// Fused: fp16 gather (R15) -> fp16 S tile in smem -> HMMA matvec.
// Per 32-node block-tile: each warp gathers 4 nodes, then computes its 16
// output columns for all 32 nodes via mma.m16n8k16 (2m x 2n x 8k = 32 mma).
// out[n] = relu((W @ S[n] + b*c[n]) / max(deg[n],1)) + alpha[n]*feat[n]
// ---------------------------------------------------------------------------
__global__ void __launch_bounds__(256, 2) fused_kernel(
    const float* __restrict__ feat, const float* __restrict__ alpha,
    const float* __restrict__ W, const float* __restrict__ b,
    float* __restrict__ out) {
    extern __shared__ __half smh[];
    __half* Wh = smh;                      // [128][SROW]  Wh[i][k] = W[i][k]
    __half* Sh = smh + 128 * SROW;         // [32][SROW]   S tile (fp16)
    float2* cdS = reinterpret_cast<float2*>(smh + 160 * SROW);  // [32] {c,deg}

    int tid = threadIdx.x, warp = tid >> 5, lane = tid & 31;

    // W -> smem fp16 (row-major, padded stride)
    for (int idx = tid; idx < D * D; idx += blockDim.x) {
        int i = idx >> 7, k = idx & (D - 1);
        Wh[i * SROW + k] = __float2half(W[idx]);
    }
    __syncthreads();

    // per-lane fragment addressing constants
    const uint32_t sbase = smem_u32(smh);
    const int a_row = (lane & 7) + ((lane >> 3) & 1) * 8;   // ldmatrix row
    const int a_kof = (lane >> 4) * 8;                      // ldmatrix k-offset
    const int b_row = warp * 16 + (lane >> 2);              // B frag output row
    const int b_kof = (lane & 3) * 2;                       // B frag k-offset
    const int colc = (lane & 3) * 2;                        // C frag column
    float2 bia[2];
    #pragma unroll
    for (int nt = 0; nt < 2; nt++)
        bia[nt] = *reinterpret_cast<const float2*>(&b[warp * 16 + nt * 8 + colc]);

    const uint2* fh = reinterpret_cast<const uint2*>(g_feat_h);
    const unsigned fullm = 0xffffffffu;

    const int numTiles = (N_NODES + 31) / 32;
    for (int tile = blockIdx.x; tile < numTiles; tile += gridDim.x) {
        int n0 = tile * 32 + warp * 4;

        // ---- gather 4 nodes per warp (R15: fp16 feat, double-buffered) ----
        int nn[4];
        #pragma unroll
        for (int r = 0; r < 4; r++) { int n = n0 + r; nn[r] = (n < N_NODES) ? n : 0; }
        int craw[4];
        #pragma unroll
        for (int r = 0; r < 4; r++) craw[r] = g_cnt[nn[r]];
        int2 pr = g_bkt[(size_t)nn[0] * MAXDEG + lane];

        #pragma unroll
        for (int r = 0; r < 4; r++) {
            int2 prn;
            if (r < 3) prn = g_bkt[(size_t)nn[r + 1] * MAXDEG + lane];

            int cnt = ((n0 + r) < N_NODES) ? min(craw[r], MAXDEG) : 0;
            float4 a = make_float4(0.f, 0.f, 0.f, 0.f);
            float c = 0.f;
            {
                int   sl = pr.x;
                float el = (lane < cnt) ? __int_as_float(pr.y) : 0.f;
                int m = min(cnt, 32);
                for (int j = 0; j < m; j += 8) {
                    int   s8[8]; float e8[8];
                    #pragma unroll
                    for (int t = 0; t < 8; t++) {
                        s8[t] = __shfl_sync(fullm, sl, j + t);
                        e8[t] = __shfl_sync(fullm, el, j + t);
                    }
                    uint2 v[8];
                    #pragma unroll
                    for (int t = 0; t < 8; t++)
                        v[t] = fh[(size_t)s8[t] * 32 + lane];
                    #pragma unroll
                    for (int t = 0; t < 8; t++) {
                        float2 f0 = bits_f2(v[t].x);
                        float2 f1 = bits_f2(v[t].y);
                        a.x += e8[t] * f0.x;
                        a.y += e8[t] * f0.y;
                        a.z += e8[t] * f1.x;
                        a.w += e8[t] * f1.y;
                        c += e8[t];
                    }
                }
            }
            if (cnt > 32) {
                const int2* bp = g_bkt + (size_t)nn[r] * MAXDEG;
                for (int base = 32; base < cnt; base += 32) {
                    int idx = base + lane;
                    int2 q2 = (idx < cnt) ? bp[idx] : make_int2(0, 0);
                    int   sl = q2.x;
                    float el = (idx < cnt) ? __int_as_float(q2.y) : 0.f;
                    int m = min(cnt - base, 32);
                    for (int j = 0; j < m; j += 8) {
                        #pragma unroll
                        for (int t = 0; t < 8; t++) {
                            int   s = __shfl_sync(fullm, sl, j + t);
                            float e = __shfl_sync(fullm, el, j + t);
                            uint2 v = fh[(size_t)s * 32 + lane];
                            float2 f0 = bits_f2(v.x);
                            float2 f1 = bits_f2(v.y);
                            a.x += e * f0.x; a.y += e * f0.y;
                            a.z += e * f1.x; a.w += e * f1.y;
                            c += e;
                        }
                    }
                }
            }
            // store S row as fp16 (8B per lane)
            uint32_t h0 = h2_bits(__floats2half2_rn(a.x, a.y));
            uint32_t h1 = h2_bits(__floats2half2_rn(a.z, a.w));
            *reinterpret_cast<uint2*>(&Sh[(warp * 4 + r) * SROW + lane * 4]) =
                make_uint2(h0, h1);
            if (lane == 0) cdS[warp * 4 + r] = make_float2(c, (float)cnt);
            pr = prn;
        }
        __syncthreads();

        // ---- HMMA matvec: 2 mtiles x 2 ntiles x 8 ktiles ----
        float acc[2][2][4];
        #pragma unroll
        for (int m = 0; m < 2; m++)
            #pragma unroll
            for (int nt = 0; nt < 2; nt++)
                #pragma unroll
                for (int q = 0; q < 4; q++) acc[m][nt][q] = 0.f;

        #pragma unroll
        for (int kt = 0; kt < 8; kt++) {
            uint32_t A[2][4];
            #pragma unroll
            for (int m = 0; m < 2; m++) {
                uint32_t addr = sbase +
                    (uint32_t)((128 * SROW + (m * 16 + a_row) * SROW + kt * 16 + a_kof) * 2);
                asm volatile(
                    "ldmatrix.sync.aligned.m8n8.x4.shared.b16 {%0,%1,%2,%3}, [%4];"
                    : "=r"(A[m][0]), "=r"(A[m][1]), "=r"(A[m][2]), "=r"(A[m][3])
                    : "r"(addr));
            }
            #pragma unroll
            for (int nt = 0; nt < 2; nt++) {
                const __half* wp = &Wh[(b_row + nt * 8) * SROW + kt * 16 + b_kof];
                uint32_t b0 = *reinterpret_cast<const uint32_t*>(wp);
                uint32_t b1 = *reinterpret_cast<const uint32_t*>(wp + 8);
                #pragma unroll
                for (int m = 0; m < 2; m++) {
                    asm volatile(
                        "mma.sync.aligned.m16n8k16.row.col.f32.f16.f16.f32 "
                        "{%0,%1,%2,%3}, {%4,%5,%6,%7}, {%8,%9}, {%0,%1,%2,%3};"
                        : "+f"(acc[m][nt][0]), "+f"(acc[m][nt][1]),
                          "+f"(acc[m][nt][2]), "+f"(acc[m][nt][3])
                        : "r"(A[m][0]), "r"(A[m][1]), "r"(A[m][2]), "r"(A[m][3]),
                          "r"(b0), "r"(b1));
                }
            }
        }

        // ---- epilogue: per-fragment-element finish ----
        int row0 = lane >> 2;
        #pragma unroll
        for (int m = 0; m < 2; m++) {
            #pragma unroll
            for (int h = 0; h < 2; h++) {
                int row = row0 + h * 8;
                int n = tile * 32 + m * 16 + row;
                if (n < N_NODES) {
                    float2 cdv = cdS[m * 16 + row];
                    float inv = 1.0f / fmaxf(cdv.y, 1.0f);
                    float cv = cdv.x;
                    float av = alpha[n];
                    #pragma unroll
                    for (int nt = 0; nt < 2; nt++) {
                        int i0 = warp * 16 + nt * 8 + colc;
                        float2 f2 = *reinterpret_cast<const float2*>(&feat[(size_t)n * D + i0]);
                        float y0 = fmaxf((acc[m][nt][h * 2 + 0] + bia[nt].x * cv) * inv, 0.f) + av * f2.x;
                        float y1 = fmaxf((acc[m][nt][h * 2 + 1] + bia[nt].y * cv) * inv, 0.f) + av * f2.y;
                        *reinterpret_cast<float2*>(&out[(size_t)n * D + i0]) = make_float2(y0, y1);
                    }
                }
            }
        }
        __syncthreads();   // protect Sh/cdS before next tile's gather
    }
}

extern "C" void kernel_launch(void* const* d_in, const int* in_sizes, int n_in,
                              void* d_out, int out_size) {
    const float* feat  = (const float*)d_in[0];
    const float* alpha = (const float*)d_in[1];
    const int*   esrc  = (const int*)d_in[2];
    const int*   edst  = (const int*)d_in[3];
    const float* ee    = (const float*)d_in[4];
    const float* W     = (const float*)d_in[5];
    const float* b     = (const float*)d_in[6];
    float* out = (float*)d_out;
    const int E = in_sizes[2];

    void* cnt_ptr = nullptr;
    cudaGetSymbolAddress(&cnt_ptr, g_cnt);
    cudaMemsetAsync(cnt_ptr, 0, N_NODES * sizeof(int));

    int fill_blocks = ((E + 3) / 4 + 255) / 256;
    prep_kernel<<<CONVB + fill_blocks, 256>>>(esrc, edst, ee, feat, E);

    // Wh 34816B + Sh 8704B + cdS 256B = 43776B
    const int smem_bytes = 160 * SROW * 2 + 32 * 8;
    cudaFuncSetAttribute(fused_kernel,
                         cudaFuncAttributeMaxDynamicSharedMemorySize, smem_bytes);
    fused_kernel<<<296, 256, smem_bytes>>>(feat, alpha, W, b, out);
}

// round 17
// speedup vs baseline: 1.4160x; 1.1231x over previous
#include <cuda_runtime.h>
#include <cuda_fp16.h>
#include <cstdint>

#define N_NODES 50000
#define D 128
#define MAXDEG 96
#define CONVB 592     // blocks of the prep kernel doing fp32->fp16 conversion
#define SROW 136      // padded row stride (halves) for W/S smem tiles

// ---- per-launch scratch (device globals) ----
__device__ int    g_cnt[N_NODES];
__device__ int2   g_bkt[N_NODES * MAXDEG];   // {src, __float_as_int(e)} per dst
__device__ __half g_feat_h[N_NODES * D];     // fp16-staged feat (12.8 MB)

// bit-cast helpers
__device__ __forceinline__ uint32_t h2_bits(__half2 h) {
    return *reinterpret_cast<uint32_t*>(&h);
}
__device__ __forceinline__ float2 bits_f2(uint32_t u) {
    __half2 h = *reinterpret_cast<__half2*>(&u);
    return __half22float2(h);
}
__device__ __forceinline__ uint32_t smem_u32(const void* p) {
    uint32_t a;
    asm("{ .reg .u64 t; cvta.to.shared.u64 t, %1; cvt.u32.u64 %0, t; }"
        : "=r"(a) : "l"(p));
    return a;
}

// ---------------------------------------------------------------------------
// Prep: blocks [0,CONVB) convert feat fp32->fp16; rest bucket-append edges.
// ---------------------------------------------------------------------------
__global__ void prep_kernel(const int* __restrict__ esrc,
                            const int* __restrict__ edst,
                            const float* __restrict__ ee,
                            const float* __restrict__ feat, int E) {
    if (blockIdx.x < CONVB) {
        int tid = blockIdx.x * blockDim.x + threadIdx.x;
        int stride = CONVB * blockDim.x;
        const float4* f4 = reinterpret_cast<const float4*>(feat);
        uint2* h4 = reinterpret_cast<uint2*>(g_feat_h);
        const int total = N_NODES * D / 4;
        for (int i = tid; i < total; i += stride) {
            float4 v = f4[i];
            uint2 o;
            o.x = h2_bits(__floats2half2_rn(v.x, v.y));
            o.y = h2_bits(__floats2half2_rn(v.z, v.w));
            h4[i] = o;
        }
        return;
    }
    int i = (blockIdx.x - CONVB) * blockDim.x + threadIdx.x;
    int base = i * 4;
    if (base + 3 < E) {
        int4   s4 = *reinterpret_cast<const int4*>(esrc + base);
        int4   d4 = *reinterpret_cast<const int4*>(edst + base);
        float4 e4 = *reinterpret_cast<const float4*>(ee + base);
        int p0 = atomicAdd(&g_cnt[d4.x], 1);
        int p1 = atomicAdd(&g_cnt[d4.y], 1);
        int p2 = atomicAdd(&g_cnt[d4.z], 1);
        int p3 = atomicAdd(&g_cnt[d4.w], 1);
        if (p0 < MAXDEG) g_bkt[d4.x * MAXDEG + p0] = make_int2(s4.x, __float_as_int(e4.x));
        if (p1 < MAXDEG) g_bkt[d4.y * MAXDEG + p1] = make_int2(s4.y, __float_as_int(e4.y));
        if (p2 < MAXDEG) g_bkt[d4.z * MAXDEG + p2] = make_int2(s4.z, __float_as_int(e4.z));
        if (p3 < MAXDEG) g_bkt[d4.w * MAXDEG + p3] = make_int2(s4.w, __float_as_int(e4.w));
    } else {
        for (int k = base; k < E; k++) {
            int d = edst[k];
            int p = atomicAdd(&g_cnt[d], 1);
            if (p < MAXDEG) g_bkt[d * MAXDEG + p] = make_int2(esrc[k], __float_as_int(ee[k]));
        }
    }
}

// ---------------------------------------------------------------------------
// Fused: fp16 gather -> fp16 S tile in smem -> HMMA matvec.
// 3 blocks/SM (24 warps) for gather latency hiding; smem 43.8KB/block.
// out[n] = relu((W @ S[n] + b*c[n]) / max(deg[n],1)) + alpha[n]*feat[n]
// ---------------------------------------------------------------------------
__global__ void __launch_bounds__(256, 3) fused_kernel(
    const float* __restrict__ feat, const float* __restrict__ alpha,
    const float* __restrict__ W, const float* __restrict__ b,
    float* __restrict__ out) {
    extern __shared__ __half smh[];
    __half* Wh = smh;                      // [128][SROW]  Wh[i][k] = W[i][k]
    __half* Sh = smh + 128 * SROW;         // [32][SROW]   S tile (fp16)
    float2* cdS = reinterpret_cast<float2*>(smh + 160 * SROW);  // [32] {c,deg}

    int tid = threadIdx.x, warp = tid >> 5, lane = tid & 31;

    // W -> smem fp16 (row-major, padded stride)
    for (int idx = tid; idx < D * D; idx += blockDim.x) {
        int i = idx >> 7, k = idx & (D - 1);
        Wh[i * SROW + k] = __float2half(W[idx]);
    }
    __syncthreads();

    // per-lane fragment addressing constants
    const uint32_t sbase = smem_u32(smh);
    const int a_row = (lane & 7) + ((lane >> 3) & 1) * 8;   // ldmatrix row
    const int a_kof = (lane >> 4) * 8;                      // ldmatrix k-offset
    const int b_row = warp * 16 + (lane >> 2);              // B frag output row
    const int b_kof = (lane & 3) * 2;                       // B frag k-offset
    const int colc = (lane & 3) * 2;                        // C frag column
    float2 bia[2];
    #pragma unroll
    for (int nt = 0; nt < 2; nt++)
        bia[nt] = *reinterpret_cast<const float2*>(&b[warp * 16 + nt * 8 + colc]);

    const uint2* fh = reinterpret_cast<const uint2*>(g_feat_h);
    const unsigned fullm = 0xffffffffu;

    const int numTiles = (N_NODES + 31) / 32;
    for (int tile = blockIdx.x; tile < numTiles; tile += gridDim.x) {
        int n0 = tile * 32 + warp * 4;

        // ---- gather 4 nodes per warp (fp16 feat, double-buffered stage) ----
        int nn[4];
        #pragma unroll
        for (int r = 0; r < 4; r++) { int n = n0 + r; nn[r] = (n < N_NODES) ? n : 0; }
        int craw[4];
        #pragma unroll
        for (int r = 0; r < 4; r++) craw[r] = g_cnt[nn[r]];
        int2 pr = g_bkt[(size_t)nn[0] * MAXDEG + lane];

        #pragma unroll
        for (int r = 0; r < 4; r++) {
            int2 prn;
            if (r < 3) prn = g_bkt[(size_t)nn[r + 1] * MAXDEG + lane];

            int cnt = ((n0 + r) < N_NODES) ? min(craw[r], MAXDEG) : 0;
            float4 a = make_float4(0.f, 0.f, 0.f, 0.f);
            float c = 0.f;
            {
                int   sl = pr.x;
                float el = (lane < cnt) ? __int_as_float(pr.y) : 0.f;
                int m = min(cnt, 32);
                for (int j = 0; j < m; j += 8) {
                    int   s8[8]; float e8[8];
                    #pragma unroll
                    for (int t = 0; t < 8; t++) {
                        s8[t] = __shfl_sync(fullm, sl, j + t);
                        e8[t] = __shfl_sync(fullm, el, j + t);
                    }
                    uint2 v[8];
                    #pragma unroll
                    for (int t = 0; t < 8; t++)
                        v[t] = fh[(size_t)s8[t] * 32 + lane];
                    #pragma unroll
                    for (int t = 0; t < 8; t++) {
                        float2 f0 = bits_f2(v[t].x);
                        float2 f1 = bits_f2(v[t].y);
                        a.x += e8[t] * f0.x;
                        a.y += e8[t] * f0.y;
                        a.z += e8[t] * f1.x;
                        a.w += e8[t] * f1.y;
                        c += e8[t];
                    }
                }
            }
            if (cnt > 32) {
                const int2* bp = g_bkt + (size_t)nn[r] * MAXDEG;
                for (int base = 32; base < cnt; base += 32) {
                    int idx = base + lane;
                    int2 q2 = (idx < cnt) ? bp[idx] : make_int2(0, 0);
                    int   sl = q2.x;
                    float el = (idx < cnt) ? __int_as_float(q2.y) : 0.f;
                    int m = min(cnt - base, 32);
                    for (int j = 0; j < m; j += 8) {
                        #pragma unroll
                        for (int t = 0; t < 8; t++) {
                            int   s = __shfl_sync(fullm, sl, j + t);
                            float e = __shfl_sync(fullm, el, j + t);
                            uint2 v = fh[(size_t)s * 32 + lane];
                            float2 f0 = bits_f2(v.x);
                            float2 f1 = bits_f2(v.y);
                            a.x += e * f0.x; a.y += e * f0.y;
                            a.z += e * f1.x; a.w += e * f1.y;
                            c += e;
                        }
                    }
                }
            }
            // store S row as fp16 (8B per lane)
            uint32_t h0 = h2_bits(__floats2half2_rn(a.x, a.y));
            uint32_t h1 = h2_bits(__floats2half2_rn(a.z, a.w));
            *reinterpret_cast<uint2*>(&Sh[(warp * 4 + r) * SROW + lane * 4]) =
                make_uint2(h0, h1);
            if (lane == 0) cdS[warp * 4 + r] = make_float2(c, (float)cnt);
            pr = prn;
        }
        __syncthreads();

        // ---- HMMA matvec: 2 mtiles x 2 ntiles x 8 ktiles ----
        float acc[2][2][4];
        #pragma unroll
        for (int m = 0; m < 2; m++)
            #pragma unroll
            for (int nt = 0; nt < 2; nt++)
                #pragma unroll
                for (int q = 0; q < 4; q++) acc[m][nt][q] = 0.f;

        #pragma unroll
        for (int kt = 0; kt < 8; kt++) {
            uint32_t A[2][4];
            #pragma unroll
            for (int m = 0; m < 2; m++) {
                uint32_t addr = sbase +
                    (uint32_t)((128 * SROW + (m * 16 + a_row) * SROW + kt * 16 + a_kof) * 2);
                asm volatile(
                    "ldmatrix.sync.aligned.m8n8.x4.shared.b16 {%0,%1,%2,%3}, [%4];"
                    : "=r"(A[m][0]), "=r"(A[m][1]), "=r"(A[m][2]), "=r"(A[m][3])
                    : "r"(addr));
            }
            #pragma unroll
            for (int nt = 0; nt < 2; nt++) {
                const __half* wp = &Wh[(b_row + nt * 8) * SROW + kt * 16 + b_kof];
                uint32_t b0 = *reinterpret_cast<const uint32_t*>(wp);
                uint32_t b1 = *reinterpret_cast<const uint32_t*>(wp + 8);
                #pragma unroll
                for (int m = 0; m < 2; m++) {
                    asm volatile(
                        "mma.sync.aligned.m16n8k16.row.col.f32.f16.f16.f32 "
                        "{%0,%1,%2,%3}, {%4,%5,%6,%7}, {%8,%9}, {%0,%1,%2,%3};"
                        : "+f"(acc[m][nt][0]), "+f"(acc[m][nt][1]),
                          "+f"(acc[m][nt][2]), "+f"(acc[m][nt][3])
                        : "r"(A[m][0]), "r"(A[m][1]), "r"(A[m][2]), "r"(A[m][3]),
                          "r"(b0), "r"(b1));
                }
            }
        }

        // ---- epilogue: per-fragment-element finish ----
        int row0 = lane >> 2;
        #pragma unroll
        for (int m = 0; m < 2; m++) {
            #pragma unroll
            for (int h = 0; h < 2; h++) {
                int row = row0 + h * 8;
                int n = tile * 32 + m * 16 + row;
                if (n < N_NODES) {
                    float2 cdv = cdS[m * 16 + row];
                    float inv = 1.0f / fmaxf(cdv.y, 1.0f);
                    float cv = cdv.x;
                    float av = alpha[n];
                    #pragma unroll
                    for (int nt = 0; nt < 2; nt++) {
                        int i0 = warp * 16 + nt * 8 + colc;
                        float2 f2 = *reinterpret_cast<const float2*>(&feat[(size_t)n * D + i0]);
                        float y0 = fmaxf((acc[m][nt][h * 2 + 0] + bia[nt].x * cv) * inv, 0.f) + av * f2.x;
                        float y1 = fmaxf((acc[m][nt][h * 2 + 1] + bia[nt].y * cv) * inv, 0.f) + av * f2.y;
                        *reinterpret_cast<float2*>(&out[(size_t)n * D + i0]) = make_float2(y0, y1);
                    }
                }
            }
        }
        __syncthreads();   // protect Sh/cdS before next tile's gather
    }
}

extern "C" void kernel_launch(void* const* d_in, const int* in_sizes, int n_in,
                              void* d_out, int out_size) {
    const float* feat  = (const float*)d_in[0];
    const float* alpha = (const float*)d_in[1];
    const int*   esrc  = (const int*)d_in[2];
    const int*   edst  = (const int*)d_in[3];
    const float* ee    = (const float*)d_in[4];
    const float* W     = (const float*)d_in[5];
    const float* b     = (const float*)d_in[6];
    float* out = (float*)d_out;
    const int E = in_sizes[2];

    void* cnt_ptr = nullptr;
    cudaGetSymbolAddress(&cnt_ptr, g_cnt);
    cudaMemsetAsync(cnt_ptr, 0, N_NODES * sizeof(int));

    int fill_blocks = ((E + 3) / 4 + 255) / 256;
    prep_kernel<<<CONVB + fill_blocks, 256>>>(esrc, edst, ee, feat, E);

    // Wh 34816B + Sh 8704B + cdS 256B = 43776B ; 3 blocks/SM
    const int smem_bytes = 160 * SROW * 2 + 32 * 8;
    cudaFuncSetAttribute(fused_kernel,
                         cudaFuncAttributeMaxDynamicSharedMemorySize, smem_bytes);
    fused_kernel<<<444, 256, smem_bytes>>>(feat, alpha, W, b, out);
}